// round 13
// baseline (speedup 1.0000x reference)
#include <cuda_runtime.h>
#include <math.h>

#define Bz 64
#define Tz 256
#define Fz 512
#define Hz 1024
#define Oz 512

// Persistent device state (transposed layouts: [feature][batch])
__device__ __align__(16) float g_hT[2][Hz * Bz];   // hidden state ping-pong, [j][b]
__device__ __align__(16) float g_cinT[Fz * Bz];    // masked input, [f][b]
__device__ int g_nsel;

__device__ __forceinline__ float sigmf(float v) { return 1.0f / (1.0f + expf(-v)); }

// Truncation split for 3xTF32: hi = x with low 13 mantissa bits cleared
// (exactly tf32-representable); lo = x - hi (exact). hi*hi + hi*lo + lo*hi
// on tensor cores gives fp32-accuracy GEMM.
__device__ __forceinline__ void split_mask(float f, unsigned& hi, unsigned& lo) {
    unsigned x = __float_as_uint(f);
    hi = x & 0xFFFFE000u;
    lo = __float_as_uint(f - __uint_as_float(hi));
}

// D += A(16x8) * B(8x8), tf32 operands, fp32 accum
__device__ __forceinline__ void mma_tf32(float* d, const unsigned* a, const unsigned* b) {
    asm volatile(
        "mma.sync.aligned.m16n8k8.row.col.f32.tf32.tf32.f32 "
        "{%0,%1,%2,%3}, {%4,%5,%6,%7}, {%8,%9}, {%0,%1,%2,%3};"
        : "+f"(d[0]), "+f"(d[1]), "+f"(d[2]), "+f"(d[3])
        : "r"(a[0]), "r"(a[1]), "r"(a[2]), "r"(a[3]), "r"(b[0]), "r"(b[1]));
}

// ---------------------------------------------------------------------------
// init: h[0] = 0, curr_in = x[:,0,:] (transposed), selw[0] = 1, nsel = 0
// ---------------------------------------------------------------------------
__global__ void init_kernel(const float* __restrict__ x, float* __restrict__ selw) {
    int i = blockIdx.x * blockDim.x + threadIdx.x;
    if (i < Hz * Bz) g_hT[0][i] = 0.0f;
    if (i < Fz * Bz) {
        int b = i >> 9;
        int f = i & 511;
        float v = x[(size_t)b * Tz * Fz + f];
        g_cinT[f * Bz + b] = v;
        selw[(size_t)b * Fz + f] = 1.0f;
    }
    if (i == 0) g_nsel = 0;
}

// ---------------------------------------------------------------------------
// gates: C[64 b x 24 v], gate-major v = gate*8 + jl, K = 512 (cin) + 1024 (h).
// 8 warps K-split: k8-step s = c*8 + w; c<8 is the input part (accNI / accNH
// split the n-gate exactly). Fragments loaded global->register with a
// TWO-chunk-deep ping-pong prefetch pipeline (load->use distance > full
// chunk of MMA+split work, covering L2 latency). Smem only for the epilogue
// cross-warp reduction.
// ---------------------------------------------------------------------------
#define GATES_SMEM (8 * 64 * 25 * 4)     // 51200 B

__global__ __launch_bounds__(256) void gates_kernel(
    int t,
    const float* __restrict__ Wih, const float* __restrict__ bih,
    const float* __restrict__ Whh, const float* __restrict__ bhh)
{
    extern __shared__ float Cred[];      // [8][64][25] pass1 / [8][64][9] pass2

    const float* __restrict__ hinT = g_hT[t & 1];
    float* __restrict__ houtT = g_hT[(t + 1) & 1];

    const int tid  = threadIdx.x;
    const int w    = tid >> 5;
    const int lane = tid & 31;
    const int g    = lane >> 2;
    const int tig  = lane & 3;
    const int j0   = blockIdx.x * 8;

    float accRZ[2][4][4] = {};   // [nf=r,z][mf][4]
    float accNI[4][4] = {};      // n-gate, input K-part (c<8)
    float accNH[4][4] = {};      // n-gate, hidden K-part

    // lane-private W row pointers (B-fragment row v = nf*8 + g)
    const float* wih_row[3];
    const float* whh_row[3];
    #pragma unroll
    for (int nf = 0; nf < 3; nf++) {
        wih_row[nf] = Wih + (size_t)(nf * Hz + j0 + g) * Fz;
        whh_row[nf] = Whh + (size_t)(nf * Hz + j0 + g) * Hz;
    }

    // two-deep register prefetch buffers
    float araw[2][4][4];
    float wraw[2][3][2];

    auto loadRaw = [&](int c, int buf) {
        int s = c * 8 + w;
        const float* A;
        int kg;
        if (s < 64) { A = g_cinT; kg = s * 8; }
        else        { A = hinT;   kg = s * 8 - 512; }
        const float* r0 = A + (size_t)(kg + tig) * Bz;
        const float* r1 = A + (size_t)(kg + tig + 4) * Bz;
        #pragma unroll
        for (int mf = 0; mf < 4; mf++) {
            araw[buf][mf][0] = r0[mf * 16 + g];
            araw[buf][mf][1] = r0[mf * 16 + 8 + g];
            araw[buf][mf][2] = r1[mf * 16 + g];
            araw[buf][mf][3] = r1[mf * 16 + 8 + g];
        }
        #pragma unroll
        for (int nf = 0; nf < 3; nf++) {
            const float* wr = (s < 64) ? (wih_row[nf] + kg) : (whh_row[nf] + kg);
            wraw[buf][nf][0] = wr[tig];
            wraw[buf][nf][1] = wr[tig + 4];
        }
    };

    auto chunk_body = [&](int c, float (&accN)[4][4]) {
        const int buf = c & 1;
        unsigned afh[4][4], afl[4][4], bfh[3][2], bfl[3][2];
        #pragma unroll
        for (int mf = 0; mf < 4; mf++)
            #pragma unroll
            for (int i = 0; i < 4; i++)
                split_mask(araw[buf][mf][i], afh[mf][i], afl[mf][i]);
        #pragma unroll
        for (int nf = 0; nf < 3; nf++)
            #pragma unroll
            for (int i = 0; i < 2; i++)
                split_mask(wraw[buf][nf][i], bfh[nf][i], bfl[nf][i]);
        if (c + 2 < 24) loadRaw(c + 2, buf);     // 2-chunk lookahead
        #pragma unroll
        for (int mf = 0; mf < 4; mf++) {
            mma_tf32(accRZ[0][mf], afh[mf], bfh[0]);
            mma_tf32(accRZ[0][mf], afh[mf], bfl[0]);
            mma_tf32(accRZ[0][mf], afl[mf], bfh[0]);
            mma_tf32(accRZ[1][mf], afh[mf], bfh[1]);
            mma_tf32(accRZ[1][mf], afh[mf], bfl[1]);
            mma_tf32(accRZ[1][mf], afl[mf], bfh[1]);
            mma_tf32(accN[mf],     afh[mf], bfh[2]);
            mma_tf32(accN[mf],     afh[mf], bfl[2]);
            mma_tf32(accN[mf],     afl[mf], bfh[2]);
        }
    };

    loadRaw(0, 0);
    loadRaw(1, 1);
    for (int c = 0; c < 8; c++)  chunk_body(c, accNI);
    for (int c = 8; c < 24; c++) chunk_body(c, accNH);

    // ---- epilogue pass 1: r (cols 0-7), z (8-15), nI (16-23) ----
    #pragma unroll
    for (int mf = 0; mf < 4; mf++) {
        int rowb = w * 1600 + (mf * 16 + g) * 25;
        #pragma unroll
        for (int nf = 0; nf < 2; nf++) {
            const float* d = accRZ[nf][mf];
            int base = rowb + nf * 8 + 2 * tig;
            Cred[base] = d[0];       Cred[base + 1] = d[1];
            Cred[base + 200] = d[2]; Cred[base + 201] = d[3];
        }
        const float* d = accNI[mf];
        int base = rowb + 16 + 2 * tig;
        Cred[base] = d[0];       Cred[base + 1] = d[1];
        Cred[base + 200] = d[2]; Cred[base + 201] = d[3];
    }
    __syncthreads();

    float sR[2], sZ[2], sNI[2], sNH[2];
    #pragma unroll
    for (int e = 0; e < 2; e++) {
        int pid = tid + e * 256;
        int b = pid & 63, jl = pid >> 6;
        sR[e] = 0.f; sZ[e] = 0.f; sNI[e] = 0.f;
        #pragma unroll
        for (int w8 = 0; w8 < 8; w8++) {
            const float* p = Cred + w8 * 1600 + b * 25;
            sR[e]  += p[jl];
            sZ[e]  += p[8 + jl];
            sNI[e] += p[16 + jl];
        }
    }
    __syncthreads();

    // ---- epilogue pass 2: nH (8 cols, pad 9) ----
    #pragma unroll
    for (int mf = 0; mf < 4; mf++) {
        const float* d = accNH[mf];
        int base = w * 576 + (mf * 16 + g) * 9 + 2 * tig;
        Cred[base] = d[0];      Cred[base + 1] = d[1];
        Cred[base + 72] = d[2]; Cred[base + 73] = d[3];
    }
    __syncthreads();
    #pragma unroll
    for (int e = 0; e < 2; e++) {
        int pid = tid + e * 256;
        int b = pid & 63, jl = pid >> 6;
        float s = 0.f;
        #pragma unroll
        for (int w8 = 0; w8 < 8; w8++) s += Cred[w8 * 576 + b * 9 + jl];
        sNH[e] = s;
    }

    // ---- GRU update ----
    #pragma unroll
    for (int e = 0; e < 2; e++) {
        int pid = tid + e * 256;
        int b = pid & 63, jl = pid >> 6;
        int j = j0 + jl;
        float br  = bih[j] + bhh[j];
        float bz  = bih[Hz + j] + bhh[Hz + j];
        float bni = bih[2 * Hz + j];
        float bnh = bhh[2 * Hz + j];
        float r = sigmf(sR[e] + br);
        float z = sigmf(sZ[e] + bz);
        float n = tanhf(sNI[e] + bni + r * (sNH[e] + bnh));
        float hp = hinT[(size_t)j * Bz + b];
        houtT[(size_t)j * Bz + b] = (1.0f - z) * n + z * hp;
    }
}

// ---------------------------------------------------------------------------
// houts: C[64 b x 8 cols] over 1024 virtual cols (512 out + 512 sel),
// K = 1024, 8-warp K-split, direct global->register fragments with 2-deep
// prefetch, 3xTF32. Sel blocks fuse the Bernoulli mask epilogue.
// ---------------------------------------------------------------------------
__global__ __launch_bounds__(256) void houts_kernel(
    int t,
    const float* __restrict__ Wout, const float* __restrict__ bout,
    const float* __restrict__ Wsel, const float* __restrict__ bsel,
    const float* __restrict__ x, const float* __restrict__ u,
    float* __restrict__ out, float* __restrict__ selw)
{
    __shared__ float Cred[8 * 576];      // [8][64][9]

    const float* __restrict__ hT = g_hT[(t + 1) & 1];

    const int tid  = threadIdx.x;
    const int w    = tid >> 5;
    const int lane = tid & 31;
    const int g    = lane >> 2;
    const int tig  = lane & 3;
    const int c0   = blockIdx.x * 8;

    // lane's B-fragment row = output column c0 + g
    const int cc = c0 + g;
    const float* __restrict__ wrow = (cc < Oz) ? (Wout + (size_t)cc * Hz)
                                               : (Wsel + (size_t)(cc - Oz) * Hz);

    float acc[4][4] = {};
    float araw[2][4][4];
    float wraw[2][2];

    auto loadRaw = [&](int c, int buf) {
        int kg = (c * 8 + w) * 8;
        const float* r0 = hT + (size_t)(kg + tig) * Bz;
        const float* r1 = hT + (size_t)(kg + tig + 4) * Bz;
        #pragma unroll
        for (int mf = 0; mf < 4; mf++) {
            araw[buf][mf][0] = r0[mf * 16 + g];
            araw[buf][mf][1] = r0[mf * 16 + 8 + g];
            araw[buf][mf][2] = r1[mf * 16 + g];
            araw[buf][mf][3] = r1[mf * 16 + 8 + g];
        }
        wraw[buf][0] = wrow[kg + tig];
        wraw[buf][1] = wrow[kg + tig + 4];
    };

    loadRaw(0, 0);
    loadRaw(1, 1);
    for (int c = 0; c < 16; c++) {
        const int buf = c & 1;
        unsigned afh[4][4], afl[4][4], bfh[2], bfl[2];
        #pragma unroll
        for (int mf = 0; mf < 4; mf++)
            #pragma unroll
            for (int i = 0; i < 4; i++)
                split_mask(araw[buf][mf][i], afh[mf][i], afl[mf][i]);
        split_mask(wraw[buf][0], bfh[0], bfl[0]);
        split_mask(wraw[buf][1], bfh[1], bfl[1]);
        if (c + 2 < 16) loadRaw(c + 2, buf);     // 2-chunk lookahead
        #pragma unroll
        for (int mf = 0; mf < 4; mf++) {
            mma_tf32(acc[mf], afh[mf], bfh);
            mma_tf32(acc[mf], afh[mf], bfl);
            mma_tf32(acc[mf], afl[mf], bfh);
        }
    }

    // ---- epilogue: 8-way reduction, then out-write or fused mask ----
    #pragma unroll
    for (int mf = 0; mf < 4; mf++) {
        const float* d = acc[mf];
        int base = w * 576 + (mf * 16 + g) * 9 + 2 * tig;
        Cred[base] = d[0];      Cred[base + 1] = d[1];
        Cred[base + 72] = d[2]; Cred[base + 73] = d[3];
    }
    __syncthreads();

    int cnt = 0;
    #pragma unroll
    for (int e = 0; e < 2; e++) {
        int pid = tid + e * 256;
        int b = pid & 63, cl = pid >> 6;
        float s = 0.f;
        #pragma unroll
        for (int w8 = 0; w8 < 8; w8++) s += Cred[w8 * 576 + b * 9 + cl];
        int c = c0 + cl;
        if (c < Oz) {
            out[(size_t)t * Bz * Oz + (size_t)b * Oz + c] = s + bout[c];
        } else if (t < Tz - 1) {
            int f = c - Oz;
            float lg = s + bsel[f];
            float sg = sigmf(lg);
            float uu = u[((size_t)(t + 1) * Bz + b) * Fz + f];
            float wv = (sg > uu) ? 1.0f : 0.0f;
            selw[((size_t)(t + 1) * Bz + b) * Fz + f] = wv;
            cnt += (int)wv;
            g_cinT[f * Bz + b] = wv * x[((size_t)b * Tz + t + 1) * Fz + f];
        }
    }
    #pragma unroll
    for (int o = 16; o; o >>= 1) cnt += __shfl_down_sync(0xffffffffu, cnt, o);
    if ((tid & 31) == 0 && cnt) atomicAdd(&g_nsel, cnt);
}

// ---------------------------------------------------------------------------
__global__ void finalize_kernel(float* __restrict__ out) {
    out[(size_t)Tz * Bz * Oz] = (float)g_nsel;
}

// ---------------------------------------------------------------------------
extern "C" void kernel_launch(void* const* d_in, const int* in_sizes, int n_in,
                              void* d_out, int out_size) {
    const float* x    = (const float*)d_in[0];
    const float* u    = (const float*)d_in[1];
    const float* Wih  = (const float*)d_in[2];
    const float* bih  = (const float*)d_in[3];
    const float* Whh  = (const float*)d_in[4];
    const float* bhh  = (const float*)d_in[5];
    const float* Wout = (const float*)d_in[6];
    const float* bout = (const float*)d_in[7];
    const float* Wsel = (const float*)d_in[8];
    const float* bsel = (const float*)d_in[9];

    float* out  = (float*)d_out;
    float* selw = out + (size_t)Tz * Bz * Oz + 1;

    cudaFuncSetAttribute(gates_kernel, cudaFuncAttributeMaxDynamicSharedMemorySize, GATES_SMEM);

    init_kernel<<<(Hz * Bz + 255) / 256, 256>>>(x, selw);
    for (int t = 0; t < Tz; t++) {
        gates_kernel<<<128, 256, GATES_SMEM>>>(t, Wih, bih, Whh, bhh);
        houts_kernel<<<128, 256>>>(t, Wout, bout, Wsel, bsel, x, u, out, selw);
    }
    finalize_kernel<<<1, 1>>>(out);
}

// round 15
// speedup vs baseline: 1.8677x; 1.8677x over previous
#include <cuda_runtime.h>
#include <math.h>

#define Bz 64
#define Tz 256
#define Fz 512
#define Hz 1024
#define Oz 512

// Fragment-ordered operand storage.
// Activations ([M=64 batch] x [K]) stored per k8-step s as:
//   flat = s*512 + mf*128 + lane*4 + i     (lane = g*4+tig, i = khalf*2+ihalf)
// so a warp's A fragments for one chunk are 4 x LDG.128, 512B contiguous.
__device__ __align__(16) float g_hF[2][Hz * Bz];   // hidden state (frag order)
__device__ __align__(16) float g_cinF[Fz * Bz];    // masked input (frag order)
// Weights reordered once per replay by prep_kernel:
// gates:  g_WgF[(bid*192 + s)*192 + nf*64 + lane*2 + khalf]   (18.9 MB)
// houts:  g_WoF[(bid*128 + s)*64 + lane*2 + khalf]            (4.2 MB)
__device__ __align__(16) float g_WgF[128ull * 192 * 192];
__device__ __align__(16) float g_WoF[128ull * 128 * 64];
__device__ int g_nsel;

__device__ __forceinline__ float sigmf(float v) { return 1.0f / (1.0f + expf(-v)); }

// frag address for activation element (k-index kk, batch b)
__device__ __forceinline__ int frag_addr(int kk, int b) {
    int s = kk >> 3, kt = kk & 7;
    int tig = kt & 3, khalf = kt >> 2;
    int mf = b >> 4, w16 = b & 15;
    int ihalf = w16 >> 3, g = w16 & 7;
    return s * 512 + mf * 128 + (g * 4 + tig) * 4 + khalf * 2 + ihalf;
}

// Truncation split for 3xTF32: hi = x with low 13 mantissa bits cleared;
// lo = x - hi (exact). hi*hi + hi*lo + lo*hi -> fp32-accuracy GEMM.
__device__ __forceinline__ void split_mask(float f, unsigned& hi, unsigned& lo) {
    unsigned x = __float_as_uint(f);
    hi = x & 0xFFFFE000u;
    lo = __float_as_uint(f - __uint_as_float(hi));
}

// D += A(16x8) * B(8x8), tf32 operands, fp32 accum
__device__ __forceinline__ void mma_tf32(float* d, const unsigned* a, const unsigned* b) {
    asm volatile(
        "mma.sync.aligned.m16n8k8.row.col.f32.tf32.tf32.f32 "
        "{%0,%1,%2,%3}, {%4,%5,%6,%7}, {%8,%9}, {%0,%1,%2,%3};"
        : "+f"(d[0]), "+f"(d[1]), "+f"(d[2]), "+f"(d[3])
        : "r"(a[0]), "r"(a[1]), "r"(a[2]), "r"(a[3]), "r"(b[0]), "r"(b[1]));
}

// ---------------------------------------------------------------------------
// prep: reorder weights into fragment order (once per replay, grid-stride)
// ---------------------------------------------------------------------------
__global__ void prep_kernel(const float* __restrict__ Wih, const float* __restrict__ Whh,
                            const float* __restrict__ Wout, const float* __restrict__ Wsel)
{
    const size_t NG = 128ull * 192 * 192;
    const size_t NO = 128ull * 128 * 64;
    for (size_t idx = (size_t)blockIdx.x * blockDim.x + threadIdx.x;
         idx < NG + NO; idx += (size_t)gridDim.x * blockDim.x) {
        if (idx < NG) {
            int bid = (int)(idx / (192 * 192));
            int r   = (int)(idx % (192 * 192));
            int s   = r / 192;
            int q   = r % 192;
            int nf  = q / 64;
            int r2  = q % 64;
            int lane = r2 >> 1, khalf = r2 & 1;
            int g = lane >> 2, tig = lane & 3;
            int row = nf * Hz + bid * 8 + g;
            int k   = s * 8 + tig + khalf * 4;
            g_WgF[idx] = (s < 64) ? Wih[(size_t)row * Fz + k]
                                  : Whh[(size_t)row * Hz + (k - 512)];
        } else {
            size_t j = idx - NG;
            int bid = (int)(j / 8192);
            int r   = (int)(j % 8192);
            int s   = r >> 6;
            int r2  = r & 63;
            int lane = r2 >> 1, khalf = r2 & 1;
            int g = lane >> 2, tig = lane & 3;
            int c = bid * 8 + g;
            int k = s * 8 + tig + khalf * 4;
            g_WoF[j] = (c < Oz) ? Wout[(size_t)c * Hz + k]
                                : Wsel[(size_t)(c - Oz) * Hz + k];
        }
    }
}

// ---------------------------------------------------------------------------
// init: h[0] = 0, cinF = x[:,0,:] (frag order), selw[0] = 1, nsel = 0
// ---------------------------------------------------------------------------
__global__ void init_kernel(const float* __restrict__ x, float* __restrict__ selw) {
    int i = blockIdx.x * blockDim.x + threadIdx.x;
    if (i < Hz * Bz) g_hF[0][i] = 0.0f;
    if (i < Fz * Bz) {
        int b = i >> 9;
        int f = i & 511;
        g_cinF[frag_addr(f, b)] = x[(size_t)b * Tz * Fz + f];
        selw[(size_t)b * Fz + f] = 1.0f;
    }
    if (i == 0) g_nsel = 0;
}

// ---------------------------------------------------------------------------
// gates: C[64 b x 24 v], gate-major, K = 512 (cin) + 1024 (h). 8 warps
// K-split (s = c*8 + w; c<8 = input part). Fragment-ordered operands:
// A = 4x LDG.128 (contiguous), W = 3x LDG.64 per chunk. 1-chunk lookahead.
// ---------------------------------------------------------------------------
#define GATES_SMEM (8 * 64 * 25 * 4)     // 51200 B

__global__ __launch_bounds__(256) void gates_kernel(
    int t, const float* __restrict__ bih, const float* __restrict__ bhh)
{
    extern __shared__ float Cred[];      // [8][64][25] pass1 / [8][64][9] pass2

    const float* __restrict__ hinF = g_hF[t & 1];
    float* __restrict__ houtF = g_hF[(t + 1) & 1];

    const int tid  = threadIdx.x;
    const int w    = tid >> 5;
    const int lane = tid & 31;
    const int j0   = blockIdx.x * 8;
    const int bid  = blockIdx.x;

    float accRZ[2][4][4] = {};
    float accNI[4][4] = {};
    float accNH[4][4] = {};

    float4 araw4[4];
    float2 wraw2[3];

    auto loadRaw = [&](int c) {
        int s = c * 8 + w;
        const float4* asrc = (s < 64)
            ? (const float4*)(g_cinF + (size_t)s * 512)
            : (const float4*)(hinF + (size_t)(s - 64) * 512);
        #pragma unroll
        for (int mf = 0; mf < 4; mf++) araw4[mf] = asrc[mf * 32 + lane];
        const float2* wsrc = (const float2*)(g_WgF + ((size_t)bid * 192 + s) * 192);
        #pragma unroll
        for (int nf = 0; nf < 3; nf++) wraw2[nf] = wsrc[nf * 32 + lane];
    };

    auto chunk_body = [&](int c, float (&accN)[4][4]) {
        unsigned afh[4][4], afl[4][4], bfh[3][2], bfl[3][2];
        #pragma unroll
        for (int mf = 0; mf < 4; mf++) {
            split_mask(araw4[mf].x, afh[mf][0], afl[mf][0]);
            split_mask(araw4[mf].y, afh[mf][1], afl[mf][1]);
            split_mask(araw4[mf].z, afh[mf][2], afl[mf][2]);
            split_mask(araw4[mf].w, afh[mf][3], afl[mf][3]);
        }
        #pragma unroll
        for (int nf = 0; nf < 3; nf++) {
            split_mask(wraw2[nf].x, bfh[nf][0], bfl[nf][0]);
            split_mask(wraw2[nf].y, bfh[nf][1], bfl[nf][1]);
        }
        if (c + 1 < 24) loadRaw(c + 1);
        #pragma unroll
        for (int mf = 0; mf < 4; mf++) {
            mma_tf32(accRZ[0][mf], afh[mf], bfh[0]);
            mma_tf32(accRZ[0][mf], afh[mf], bfl[0]);
            mma_tf32(accRZ[0][mf], afl[mf], bfh[0]);
            mma_tf32(accRZ[1][mf], afh[mf], bfh[1]);
            mma_tf32(accRZ[1][mf], afh[mf], bfl[1]);
            mma_tf32(accRZ[1][mf], afl[mf], bfh[1]);
            mma_tf32(accN[mf],     afh[mf], bfh[2]);
            mma_tf32(accN[mf],     afh[mf], bfl[2]);
            mma_tf32(accN[mf],     afl[mf], bfh[2]);
        }
    };

    loadRaw(0);
    for (int c = 0; c < 8; c++)  chunk_body(c, accNI);
    for (int c = 8; c < 24; c++) chunk_body(c, accNH);

    const int g   = lane >> 2;
    const int tig = lane & 3;

    // ---- epilogue pass 1: r (cols 0-7), z (8-15), nI (16-23) ----
    #pragma unroll
    for (int mf = 0; mf < 4; mf++) {
        int rowb = w * 1600 + (mf * 16 + g) * 25;
        #pragma unroll
        for (int nf = 0; nf < 2; nf++) {
            const float* d = accRZ[nf][mf];
            int base = rowb + nf * 8 + 2 * tig;
            Cred[base] = d[0];       Cred[base + 1] = d[1];
            Cred[base + 200] = d[2]; Cred[base + 201] = d[3];
        }
        const float* d = accNI[mf];
        int base = rowb + 16 + 2 * tig;
        Cred[base] = d[0];       Cred[base + 1] = d[1];
        Cred[base + 200] = d[2]; Cred[base + 201] = d[3];
    }
    __syncthreads();

    float sR[2], sZ[2], sNI[2], sNH[2];
    #pragma unroll
    for (int e = 0; e < 2; e++) {
        int pid = tid + e * 256;
        int b = pid & 63, jl = pid >> 6;
        sR[e] = 0.f; sZ[e] = 0.f; sNI[e] = 0.f;
        #pragma unroll
        for (int w8 = 0; w8 < 8; w8++) {
            const float* p = Cred + w8 * 1600 + b * 25;
            sR[e]  += p[jl];
            sZ[e]  += p[8 + jl];
            sNI[e] += p[16 + jl];
        }
    }
    __syncthreads();

    // ---- epilogue pass 2: nH ----
    #pragma unroll
    for (int mf = 0; mf < 4; mf++) {
        const float* d = accNH[mf];
        int base = w * 576 + (mf * 16 + g) * 9 + 2 * tig;
        Cred[base] = d[0];      Cred[base + 1] = d[1];
        Cred[base + 72] = d[2]; Cred[base + 73] = d[3];
    }
    __syncthreads();
    #pragma unroll
    for (int e = 0; e < 2; e++) {
        int pid = tid + e * 256;
        int b = pid & 63, jl = pid >> 6;
        float s = 0.f;
        #pragma unroll
        for (int w8 = 0; w8 < 8; w8++) s += Cred[w8 * 576 + b * 9 + jl];
        sNH[e] = s;
    }

    // ---- GRU update (writes fragment-ordered h) ----
    #pragma unroll
    for (int e = 0; e < 2; e++) {
        int pid = tid + e * 256;
        int b = pid & 63, jl = pid >> 6;
        int j = j0 + jl;
        float br  = bih[j] + bhh[j];
        float bz  = bih[Hz + j] + bhh[Hz + j];
        float bni = bih[2 * Hz + j];
        float bnh = bhh[2 * Hz + j];
        float r = sigmf(sR[e] + br);
        float z = sigmf(sZ[e] + bz);
        float n = tanhf(sNI[e] + bni + r * (sNH[e] + bnh));
        int fa = frag_addr(j, b);
        float hp = hinF[fa];
        houtF[fa] = (1.0f - z) * n + z * hp;
    }
}

// ---------------------------------------------------------------------------
// houts: C[64 b x 8 cols] over 1024 virtual cols, K = 1024, 8-warp K-split,
// fragment-ordered operands (A 4x LDG.128, W 1x LDG.64). Sel blocks fuse the
// Bernoulli mask epilogue (writes cinF fragment-ordered).
// ---------------------------------------------------------------------------
__global__ __launch_bounds__(256) void houts_kernel(
    int t,
    const float* __restrict__ bout, const float* __restrict__ bsel,
    const float* __restrict__ x, const float* __restrict__ u,
    float* __restrict__ out, float* __restrict__ selw)
{
    __shared__ float Cred[8 * 576];      // [8][64][9]

    const float* __restrict__ hF = g_hF[(t + 1) & 1];

    const int tid  = threadIdx.x;
    const int w    = tid >> 5;
    const int lane = tid & 31;
    const int c0   = blockIdx.x * 8;
    const int bid  = blockIdx.x;

    float acc[4][4] = {};
    float4 araw4[4];
    float2 wraw2;

    auto loadRaw = [&](int c) {
        int s = c * 8 + w;
        const float4* asrc = (const float4*)(hF + (size_t)s * 512);
        #pragma unroll
        for (int mf = 0; mf < 4; mf++) araw4[mf] = asrc[mf * 32 + lane];
        wraw2 = ((const float2*)(g_WoF + ((size_t)bid * 128 + s) * 64))[lane];
    };

    loadRaw(0);
    for (int c = 0; c < 16; c++) {
        unsigned afh[4][4], afl[4][4], bfh[2], bfl[2];
        #pragma unroll
        for (int mf = 0; mf < 4; mf++) {
            split_mask(araw4[mf].x, afh[mf][0], afl[mf][0]);
            split_mask(araw4[mf].y, afh[mf][1], afl[mf][1]);
            split_mask(araw4[mf].z, afh[mf][2], afl[mf][2]);
            split_mask(araw4[mf].w, afh[mf][3], afl[mf][3]);
        }
        split_mask(wraw2.x, bfh[0], bfl[0]);
        split_mask(wraw2.y, bfh[1], bfl[1]);
        if (c + 1 < 16) loadRaw(c + 1);
        #pragma unroll
        for (int mf = 0; mf < 4; mf++) {
            mma_tf32(acc[mf], afh[mf], bfh);
            mma_tf32(acc[mf], afh[mf], bfl);
            mma_tf32(acc[mf], afl[mf], bfh);
        }
    }

    const int g   = lane >> 2;
    const int tig = lane & 3;

    // ---- epilogue: 8-way reduction, then out-write or fused mask ----
    #pragma unroll
    for (int mf = 0; mf < 4; mf++) {
        const float* d = acc[mf];
        int base = w * 576 + (mf * 16 + g) * 9 + 2 * tig;
        Cred[base] = d[0];      Cred[base + 1] = d[1];
        Cred[base + 72] = d[2]; Cred[base + 73] = d[3];
    }
    __syncthreads();

    int cnt = 0;
    #pragma unroll
    for (int e = 0; e < 2; e++) {
        int pid = tid + e * 256;
        int b = pid & 63, cl = pid >> 6;
        float s = 0.f;
        #pragma unroll
        for (int w8 = 0; w8 < 8; w8++) s += Cred[w8 * 576 + b * 9 + cl];
        int c = c0 + cl;
        if (c < Oz) {
            out[(size_t)t * Bz * Oz + (size_t)b * Oz + c] = s + bout[c];
        } else if (t < Tz - 1) {
            int f = c - Oz;
            float lg = s + bsel[f];
            float sg = sigmf(lg);
            float uu = u[((size_t)(t + 1) * Bz + b) * Fz + f];
            float wv = (sg > uu) ? 1.0f : 0.0f;
            selw[((size_t)(t + 1) * Bz + b) * Fz + f] = wv;
            cnt += (int)wv;
            g_cinF[frag_addr(f, b)] = wv * x[((size_t)b * Tz + t + 1) * Fz + f];
        }
    }
    #pragma unroll
    for (int o = 16; o; o >>= 1) cnt += __shfl_down_sync(0xffffffffu, cnt, o);
    if ((tid & 31) == 0 && cnt) atomicAdd(&g_nsel, cnt);
}

// ---------------------------------------------------------------------------
__global__ void finalize_kernel(float* __restrict__ out) {
    out[(size_t)Tz * Bz * Oz] = (float)g_nsel;
}

// ---------------------------------------------------------------------------
extern "C" void kernel_launch(void* const* d_in, const int* in_sizes, int n_in,
                              void* d_out, int out_size) {
    const float* x    = (const float*)d_in[0];
    const float* u    = (const float*)d_in[1];
    const float* Wih  = (const float*)d_in[2];
    const float* bih  = (const float*)d_in[3];
    const float* Whh  = (const float*)d_in[4];
    const float* bhh  = (const float*)d_in[5];
    const float* Wout = (const float*)d_in[6];
    const float* bout = (const float*)d_in[7];
    const float* Wsel = (const float*)d_in[8];
    const float* bsel = (const float*)d_in[9];

    float* out  = (float*)d_out;
    float* selw = out + (size_t)Tz * Bz * Oz + 1;

    cudaFuncSetAttribute(gates_kernel, cudaFuncAttributeMaxDynamicSharedMemorySize, GATES_SMEM);

    prep_kernel<<<1024, 256>>>(Wih, Whh, Wout, Wsel);
    init_kernel<<<(Hz * Bz + 255) / 256, 256>>>(x, selw);
    for (int t = 0; t < Tz; t++) {
        gates_kernel<<<128, 256, GATES_SMEM>>>(t, bih, bhh);
        houts_kernel<<<128, 256>>>(t, bout, bsel, x, u, out, selw);
    }
    finalize_kernel<<<1, 1>>>(out);
}